// round 2
// baseline (speedup 1.0000x reference)
#include <cuda_runtime.h>
#include <cuda_bf16.h>
#include <math.h>
#include <stdint.h>

#define B_ 64
#define C_ 256
#define T_ 32
#define HW_ 49
#define N_ 1568      // T_*HW_
#define KV_ 97
#define KN_ 300
#define D_ 512
#define NTOK_ 392

// ---------------- scratch (device globals: allocation-free) ----------------
__device__ float g_cam[B_ * N_];                                   // 401 KB
__device__ __nv_bfloat16 g_xT[(size_t)B_ * T_ * HW_ * C_];          // 51.4 MB
__device__ __nv_bfloat16 g_W[9 * D_ * C_];                          // 2.36 MB
__device__ float g_loss;

// ---------------- helpers ----------------
__device__ __forceinline__ void mma16816(float* c, const uint32_t* a,
                                         uint32_t b0, uint32_t b1) {
    asm volatile(
        "mma.sync.aligned.m16n8k16.row.col.f32.bf16.bf16.f32 "
        "{%0,%1,%2,%3}, {%4,%5,%6,%7}, {%8,%9}, {%0,%1,%2,%3};\n"
        : "+f"(c[0]), "+f"(c[1]), "+f"(c[2]), "+f"(c[3])
        : "r"(a[0]), "r"(a[1]), "r"(a[2]), "r"(a[3]), "r"(b0), "r"(b1));
}

__device__ __forceinline__ void cp_async16(uint32_t smem_addr, const void* gptr) {
    asm volatile("cp.async.cg.shared.global [%0], [%1], 16;\n"
                 :: "r"(smem_addr), "l"(gptr));
}
__device__ __forceinline__ void cp_commit() { asm volatile("cp.async.commit_group;\n"); }
__device__ __forceinline__ void cp_wait0()  { asm volatile("cp.async.wait_group 0;\n"); }

// ---------------- kernel 0: weight transpose  conv_w(D,C,1,3,3) -> Wt[tap][d][c] bf16
__global__ void prep_w_kernel(const float* __restrict__ conv_w) {
    int idx = blockIdx.x * blockDim.x + threadIdx.x;
    const int total = 9 * D_ * C_;
    if (idx >= total) return;
    int c = idx % C_;
    int d = (idx / C_) % D_;
    int tap = idx / (C_ * D_);
    g_W[idx] = __float2bfloat16(conv_w[(d * C_ + c) * 9 + tap]);
}

// ---------------- kernel 1: x transpose  x(B,C,T,HW) -> xT[b,t,pos,c] bf16
__global__ void prep_x_kernel(const float* __restrict__ x) {
    __shared__ __nv_bfloat16 sm[C_ * HW_];
    int bt = blockIdx.x;
    int b = bt / T_, t = bt % T_;
    const float* src = x + (size_t)b * C_ * (T_ * HW_) + (size_t)t * HW_;
    for (int i = threadIdx.x; i < C_ * HW_; i += 256) {
        int c = i / HW_, p = i % HW_;
        sm[i] = __float2bfloat16(src[(size_t)c * (T_ * HW_) + p]);
    }
    __syncthreads();
    __nv_bfloat16* dst = g_xT + (size_t)bt * HW_ * C_;
    for (int i = threadIdx.x; i < C_ * HW_; i += 256) {
        int p = i / C_, c = i % C_;
        dst[i] = sm[c * HW_ + p];
    }
}

// ---------------- kernel 2: CAM (one block per sample) ----------------
__global__ void cam_kernel(const float* __restrict__ x,
                           const float* __restrict__ lv, const float* __restrict__ ln,
                           const float* __restrict__ wpv, const float* __restrict__ wpn) {
    __shared__ float w_v[C_], w_n[C_];
    __shared__ float rv[N_], rn[N_];
    __shared__ float sbuf[2048];
    __shared__ float red[256];
    __shared__ int redi[256];
    __shared__ float thrs[2];

    int b = blockIdx.x;
    int tid = threadIdx.x;

    // argmax of each logit row; gather its weight row
    for (int br = 0; br < 2; ++br) {
        const float* lg = br ? ln : lv;
        int K = br ? KN_ : KV_;
        const float* wp = br ? wpn : wpv;
        float best = -INFINITY; int bi = 0x7fffffff;
        for (int i = tid; i < K; i += 256) {
            float v = lg[b * K + i];
            if (v > best || (v == best && i < bi)) { best = v; bi = i; }
        }
        red[tid] = best; redi[tid] = bi;
        __syncthreads();
        for (int s = 128; s > 0; s >>= 1) {
            if (tid < s) {
                float ov = red[tid + s]; int oi = redi[tid + s];
                if (ov > red[tid] || (ov == red[tid] && oi < redi[tid])) {
                    red[tid] = ov; redi[tid] = oi;
                }
            }
            __syncthreads();
        }
        int top = redi[0];
        __syncthreads();
        float* wdst = br ? w_n : w_v;
        wdst[tid] = wp[top * C_ + tid];   // C_ == 256 == blockDim
        __syncthreads();
    }

    // dual projection: row[n] = sum_c w[c]*x[b,c,n]   (x read once for both)
    const float* xb = x + (size_t)b * C_ * N_;
    float av[7], an[7];
#pragma unroll
    for (int i = 0; i < 7; ++i) { av[i] = 0.f; an[i] = 0.f; }
    for (int c = 0; c < C_; ++c) {
        float wv_ = w_v[c], wn_ = w_n[c];
        const float* xc = xb + (size_t)c * N_;
#pragma unroll
        for (int i = 0; i < 7; ++i) {
            int n = tid + i * 256;
            if (n < N_) {
                float xv = __ldg(xc + n);
                av[i] += wv_ * xv;
                an[i] += wn_ * xv;
            }
        }
    }
#pragma unroll
    for (int i = 0; i < 7; ++i) {
        int n = tid + i * 256;
        if (n < N_) { rv[n] = av[i]; rn[n] = an[i]; }
    }
    __syncthreads();

    // per branch: min-max normalize + find 392nd-largest threshold (bitonic)
    for (int br = 0; br < 2; ++br) {
        float* r = br ? rn : rv;
        float mn = INFINITY, mx = -INFINITY;
        for (int n = tid; n < N_; n += 256) { float v = r[n]; mn = fminf(mn, v); mx = fmaxf(mx, v); }
        red[tid] = mn; sbuf[tid] = mx;
        __syncthreads();
        for (int s = 128; s > 0; s >>= 1) {
            if (tid < s) { red[tid] = fminf(red[tid], red[tid + s]); sbuf[tid] = fmaxf(sbuf[tid], sbuf[tid + s]); }
            __syncthreads();
        }
        mn = red[0]; mx = sbuf[0];
        __syncthreads();
        float inv = 1.0f / (mx - mn);
        for (int n = tid; n < N_; n += 256) r[n] = (r[n] - mn) * inv;
        __syncthreads();
        for (int i = tid; i < 2048; i += 256) sbuf[i] = (i < N_) ? r[i] : -INFINITY;
        __syncthreads();
        // ascending bitonic sort of 2048
        for (int k = 2; k <= 2048; k <<= 1) {
            for (int j = k >> 1; j > 0; j >>= 1) {
                for (int i = tid; i < 2048; i += 256) {
                    int ixj = i ^ j;
                    if (ixj > i) {
                        bool up = ((i & k) == 0);
                        float a0 = sbuf[i], b0 = sbuf[ixj];
                        if ((a0 > b0) == up) { sbuf[i] = b0; sbuf[ixj] = a0; }
                    }
                }
                __syncthreads();
            }
        }
        if (tid == 0) thrs[br] = sbuf[2048 - NTOK_];
        __syncthreads();
    }

    float tv = thrs[0], tn = thrs[1];
    for (int n = tid; n < N_; n += 256) {
        float a = rv[n]; a = (a >= tv) ? a : 0.0f;
        float c2 = rn[n]; c2 = (c2 >= tn) ? c2 : 0.0f;
        g_cam[b * N_ + n] = fmaxf(a, c2);
    }
}

// ---------------- kernel 3/5: loss init / finalize ----------------
__global__ void init_kernel() { g_loss = 0.0f; }
__global__ void final_kernel(float* out) { out[0] = g_loss * (1.0f / (float)(B_ * N_)); }

// ---------------- kernel 4: conv-GEMM + ReLU + score + BCE ----------------
// Block tile: M=128 (two t-slices of one b, each padded 49->64), N=512 (4x128), K=2304.
// A = implicit im2col via per-row pointers into the shared x slice (row 98 = zeros).
#define XSTR 264          // xsm row stride (bf16 elems), conflict-free
#define WSTR 72           // wsm row stride (bf16 elems), conflict-free
#define XSM_BYTES (99 * XSTR * 2)           // 52272 -> pad 52288
#define WSM_OFF   52288
#define WSM_BYTES (2 * 128 * WSTR * 2)      // 36864
#define SROW_OFF  (WSM_OFF + WSM_BYTES)     // 89152
#define SWSM_OFF  (SROW_OFF + 512)
#define CBSM_OFF  (SWSM_OFF + 2048)
#define REDB_OFF  (CBSM_OFF + 2048)
#define SMEM_GEMM (REDB_OFF + 64)

__global__ __launch_bounds__(256, 2)
void gemm_kernel(const float* __restrict__ conv_b,
                 const float* __restrict__ score_w,
                 const float* __restrict__ score_b) {
    extern __shared__ char smem[];
    __nv_bfloat16* xsm = (__nv_bfloat16*)smem;
    __nv_bfloat16* wsm = (__nv_bfloat16*)(smem + WSM_OFF);
    float* srow = (float*)(smem + SROW_OFF);
    float* swsm = (float*)(smem + SWSM_OFF);
    float* cbsm = (float*)(smem + CBSM_OFF);
    float* redb = (float*)(smem + REDB_OFF);

    int tid = threadIdx.x;
    int lane = tid & 31, wid = tid >> 5;
    int g = lane >> 2, tg = lane & 3;
    int warp_m = wid & 3, warp_n = wid >> 2;
    int m_base = warp_m * 32;

    int blk = blockIdx.x;
    int b = blk >> 4;
    int t0 = (blk & 15) * 2;

    // ---- fill x slice (rows 0..97 data, row 98 zeros) ----
    for (int i = tid; i < 98 * 32; i += 256) {
        int row = i >> 5, seg = i & 31;
        int slice = (row >= 49) ? 1 : 0;
        int pos = row - slice * 49;
        const __nv_bfloat16* src =
            g_xT + ((size_t)((b * T_ + t0 + slice) * HW_ + pos)) * C_ + seg * 8;
        *(uint4*)(xsm + row * XSTR + seg * 8) = *(const uint4*)src;
    }
    if (tid < 128) ((uint32_t*)(xsm + 98 * XSTR))[tid] = 0u;
    for (int i = tid; i < 512; i += 256) { swsm[i] = score_w[i]; cbsm[i] = conv_b[i]; }
    if (tid < 128) srow[tid] = 0.0f;

    int wrow = tid >> 1, wseg = tid & 1;   // weight-tile loader role: 2 threads/row

    for (int nt = 0; nt < 4; ++nt) {
        int d_tile = nt * 128;
        float acc[2][8][4];
#pragma unroll
        for (int mf = 0; mf < 2; ++mf)
#pragma unroll
            for (int nf = 0; nf < 8; ++nf)
#pragma unroll
                for (int q = 0; q < 4; ++q) acc[mf][nf][q] = 0.0f;

        // prologue: stage 0 weights -> wsm[0]
        {
            const uint4* src = (const uint4*)(g_W + ((size_t)(d_tile + wrow)) * C_ + wseg * 32);
            uint4* dst = (uint4*)(wsm + wrow * WSTR + wseg * 32);
#pragma unroll
            for (int q = 0; q < 4; ++q) dst[q] = src[q];
        }
        __syncthreads();

        int buf = 0;
        for (int s = 0; s < 36; ++s) {
            int tap = s >> 2;
            int c0 = (s & 3) << 6;

            // async prefetch next weight tile into other buffer
            int sn = s + 1;
            if (sn < 36) {
                int tapn = sn >> 2, c0n = (sn & 3) << 6;
                const __nv_bfloat16* src =
                    g_W + ((size_t)(tapn * D_ + d_tile + wrow)) * C_ + c0n + wseg * 32;
                uint32_t dsts = (uint32_t)__cvta_generic_to_shared(
                    wsm + (buf ^ 1) * (128 * WSTR) + wrow * WSTR + wseg * 32);
#pragma unroll
                for (int q = 0; q < 4; ++q) cp_async16(dsts + q * 16, src + q * 8);
                cp_commit();
            }

            // per-tap A row offsets (shifted conv window; OOB/pad -> zero row 98)
            int dh = tap / 3 - 1, dw = tap % 3 - 1;
            int aoff[2][2];
#pragma unroll
            for (int mf = 0; mf < 2; ++mf) {
#pragma unroll
                for (int hh = 0; hh < 2; ++hh) {
                    int r = m_base + mf * 16 + hh * 8 + g;
                    int slice = r >> 6, pos = r & 63;
                    int xr = 98;
                    if (pos < 49) {
                        int h = pos / 7, w = pos % 7;
                        int ph = h + dh, pw = w + dw;
                        if (ph >= 0 && ph < 7 && pw >= 0 && pw < 7)
                            xr = slice * 49 + ph * 7 + pw;
                    }
                    aoff[mf][hh] = xr * XSTR;
                }
            }

            const __nv_bfloat16* wb = wsm + buf * (128 * WSTR);
#pragma unroll
            for (int k16 = 0; k16 < 4; ++k16) {
                int kl = k16 * 16;
                uint32_t a[2][4];
#pragma unroll
                for (int mf = 0; mf < 2; ++mf) {
                    int cA = c0 + kl + tg * 2;
                    a[mf][0] = *(const uint32_t*)(xsm + aoff[mf][0] + cA);
                    a[mf][1] = *(const uint32_t*)(xsm + aoff[mf][1] + cA);
                    a[mf][2] = *(const uint32_t*)(xsm + aoff[mf][0] + cA + 8);
                    a[mf][3] = *(const uint32_t*)(xsm + aoff[mf][1] + cA + 8);
                }
#pragma unroll
                for (int nf = 0; nf < 8; ++nf) {
                    int nrow = warp_n * 64 + nf * 8 + g;
                    uint32_t b0 = *(const uint32_t*)(wb + nrow * WSTR + kl + tg * 2);
                    uint32_t b1 = *(const uint32_t*)(wb + nrow * WSTR + kl + tg * 2 + 8);
                    mma16816(acc[0][nf], a[0], b0, b1);
                    mma16816(acc[1][nf], a[1], b0, b1);
                }
            }

            cp_wait0();
            __syncthreads();
            buf ^= 1;
        }

        // epilogue: fused bias + ReLU + score_w dot, accumulate per-row
#pragma unroll
        for (int mf = 0; mf < 2; ++mf) {
            float p0 = 0.f, p1 = 0.f;
#pragma unroll
            for (int nf = 0; nf < 8; ++nf) {
                int d = d_tile + warp_n * 64 + nf * 8 + tg * 2;
                float cb0 = cbsm[d], cb1 = cbsm[d + 1];
                float sw0 = swsm[d], sw1 = swsm[d + 1];
                p0 += sw0 * fmaxf(acc[mf][nf][0] + cb0, 0.f)
                    + sw1 * fmaxf(acc[mf][nf][1] + cb1, 0.f);
                p1 += sw0 * fmaxf(acc[mf][nf][2] + cb0, 0.f)
                    + sw1 * fmaxf(acc[mf][nf][3] + cb1, 0.f);
            }
            p0 += __shfl_xor_sync(0xffffffff, p0, 1);
            p0 += __shfl_xor_sync(0xffffffff, p0, 2);
            p1 += __shfl_xor_sync(0xffffffff, p1, 1);
            p1 += __shfl_xor_sync(0xffffffff, p1, 2);
            if (tg == 0) {
                atomicAdd(&srow[m_base + mf * 16 + g], p0);
                atomicAdd(&srow[m_base + mf * 16 + 8 + g], p1);
            }
        }
        __syncthreads();
    }

    // ---- BCE over the 98 valid rows, block-reduce, one global atomic ----
    float lsum = 0.0f;
    if (tid < 128) {
        int slice = tid >> 6, pos = tid & 63;
        if (pos < 49) {
            float sl = srow[tid] + score_b[0];
            int t = t0 + slice;
            float y = g_cam[b * N_ + t * HW_ + pos];
            float bce = log1pf(expf(-fabsf(sl)))
                      + ((sl > 0.f) ? (1.f - y) * sl : -sl * y);
            lsum = bce;
        }
    }
#pragma unroll
    for (int o = 16; o > 0; o >>= 1) lsum += __shfl_xor_sync(0xffffffff, lsum, o);
    if (lane == 0) redb[wid] = lsum;
    __syncthreads();
    if (tid == 0) {
        float s2 = 0.f;
#pragma unroll
        for (int i = 0; i < 8; ++i) s2 += redb[i];
        atomicAdd(&g_loss, s2);
    }
}

// ---------------- launcher ----------------
extern "C" void kernel_launch(void* const* d_in, const int* in_sizes, int n_in,
                              void* d_out, int out_size) {
    const float* x        = (const float*)d_in[0];
    const float* lv       = (const float*)d_in[1];
    const float* ln       = (const float*)d_in[2];
    const float* wpv      = (const float*)d_in[3];
    const float* wpn      = (const float*)d_in[4];
    const float* conv_w   = (const float*)d_in[5];
    const float* conv_b   = (const float*)d_in[6];
    const float* score_w  = (const float*)d_in[7];
    const float* score_b  = (const float*)d_in[8];
    float* out = (float*)d_out;

    cudaFuncSetAttribute(gemm_kernel, cudaFuncAttributeMaxDynamicSharedMemorySize, SMEM_GEMM);

    prep_w_kernel<<<(9 * D_ * C_ + 255) / 256, 256>>>(conv_w);
    prep_x_kernel<<<B_ * T_, 256>>>(x);
    cam_kernel<<<B_, 256>>>(x, lv, ln, wpv, wpn);
    init_kernel<<<1, 1>>>();
    gemm_kernel<<<B_ * T_ / 2, 256, SMEM_GEMM>>>(conv_b, score_w, score_b);
    final_kernel<<<1, 1>>>(out);
}

// round 4
// speedup vs baseline: 1.0001x; 1.0001x over previous
#include <cuda_runtime.h>
#include <cuda_bf16.h>
#include <math.h>
#include <stdint.h>

#define B_ 64
#define C_ 256
#define T_ 32
#define HW_ 49
#define N_ 1568      // T_*HW_
#define KV_ 97
#define KN_ 300
#define D_ 512
#define NTOK_ 392

// ---------------- scratch (device globals: allocation-free) ----------------
__device__ float g_cam[B_ * N_];                                   // 401 KB
__device__ __nv_bfloat16 g_xT[(size_t)B_ * T_ * HW_ * C_];          // 51.4 MB
__device__ __nv_bfloat16 g_W[9 * D_ * C_];                          // 2.36 MB
__device__ float g_loss;

// ---------------- helpers ----------------
__device__ __forceinline__ void mma16816(float* c, const uint32_t* a,
                                         uint32_t b0, uint32_t b1) {
    asm volatile(
        "mma.sync.aligned.m16n8k16.row.col.f32.bf16.bf16.f32 "
        "{%0,%1,%2,%3}, {%4,%5,%6,%7}, {%8,%9}, {%0,%1,%2,%3};\n"
        : "+f"(c[0]), "+f"(c[1]), "+f"(c[2]), "+f"(c[3])
        : "r"(a[0]), "r"(a[1]), "r"(a[2]), "r"(a[3]), "r"(b0), "r"(b1));
}

__device__ __forceinline__ void cp_async16(uint32_t smem_addr, const void* gptr) {
    asm volatile("cp.async.cg.shared.global [%0], [%1], 16;\n"
                 :: "r"(smem_addr), "l"(gptr));
}
__device__ __forceinline__ void cp_commit() { asm volatile("cp.async.commit_group;\n"); }
__device__ __forceinline__ void cp_wait0()  { asm volatile("cp.async.wait_group 0;\n"); }

// ---------------- kernel 0: weight transpose  conv_w(D,C,1,3,3) -> Wt[tap][d][c] bf16
__global__ void prep_w_kernel(const float* __restrict__ conv_w) {
    int idx = blockIdx.x * blockDim.x + threadIdx.x;
    const int total = 9 * D_ * C_;
    if (idx >= total) return;
    int c = idx % C_;
    int d = (idx / C_) % D_;
    int tap = idx / (C_ * D_);
    g_W[idx] = __float2bfloat16(conv_w[(d * C_ + c) * 9 + tap]);
}

// ---------------- kernel 1: x transpose  x(B,C,T,HW) -> xT[b,t,pos,c] bf16
__global__ void prep_x_kernel(const float* __restrict__ x) {
    __shared__ __nv_bfloat16 sm[C_ * HW_];
    int bt = blockIdx.x;
    int b = bt / T_, t = bt % T_;
    const float* src = x + (size_t)b * C_ * (T_ * HW_) + (size_t)t * HW_;
    for (int i = threadIdx.x; i < C_ * HW_; i += 256) {
        int c = i / HW_, p = i % HW_;
        sm[i] = __float2bfloat16(src[(size_t)c * (T_ * HW_) + p]);
    }
    __syncthreads();
    __nv_bfloat16* dst = g_xT + (size_t)bt * HW_ * C_;
    for (int i = threadIdx.x; i < C_ * HW_; i += 256) {
        int p = i / C_, c = i % C_;
        dst[i] = sm[c * HW_ + p];
    }
}

// ---------------- kernel 2: CAM (one block per sample) ----------------
__global__ void cam_kernel(const float* __restrict__ x,
                           const float* __restrict__ lv, const float* __restrict__ ln,
                           const float* __restrict__ wpv, const float* __restrict__ wpn) {
    __shared__ float w_v[C_], w_n[C_];
    __shared__ float rv[N_], rn[N_];
    __shared__ float sbuf[2048];
    __shared__ float red[256];
    __shared__ int redi[256];
    __shared__ float thrs[2];

    int b = blockIdx.x;
    int tid = threadIdx.x;

    // argmax of each logit row; gather its weight row
    for (int br = 0; br < 2; ++br) {
        const float* lg = br ? ln : lv;
        int K = br ? KN_ : KV_;
        const float* wp = br ? wpn : wpv;
        float best = -INFINITY; int bi = 0x7fffffff;
        for (int i = tid; i < K; i += 256) {
            float v = lg[b * K + i];
            if (v > best || (v == best && i < bi)) { best = v; bi = i; }
        }
        red[tid] = best; redi[tid] = bi;
        __syncthreads();
        for (int s = 128; s > 0; s >>= 1) {
            if (tid < s) {
                float ov = red[tid + s]; int oi = redi[tid + s];
                if (ov > red[tid] || (ov == red[tid] && oi < redi[tid])) {
                    red[tid] = ov; redi[tid] = oi;
                }
            }
            __syncthreads();
        }
        int top = redi[0];
        __syncthreads();
        float* wdst = br ? w_n : w_v;
        wdst[tid] = wp[top * C_ + tid];   // C_ == 256 == blockDim
        __syncthreads();
    }

    // dual projection: row[n] = sum_c w[c]*x[b,c,n]   (x read once for both)
    const float* xb = x + (size_t)b * C_ * N_;
    float av[7], an[7];
#pragma unroll
    for (int i = 0; i < 7; ++i) { av[i] = 0.f; an[i] = 0.f; }
    for (int c = 0; c < C_; ++c) {
        float wv_ = w_v[c], wn_ = w_n[c];
        const float* xc = xb + (size_t)c * N_;
#pragma unroll
        for (int i = 0; i < 7; ++i) {
            int n = tid + i * 256;
            if (n < N_) {
                float xv = __ldg(xc + n);
                av[i] += wv_ * xv;
                an[i] += wn_ * xv;
            }
        }
    }
#pragma unroll
    for (int i = 0; i < 7; ++i) {
        int n = tid + i * 256;
        if (n < N_) { rv[n] = av[i]; rn[n] = an[i]; }
    }
    __syncthreads();

    // per branch: min-max normalize + find 392nd-largest threshold (bitonic)
    for (int br = 0; br < 2; ++br) {
        float* r = br ? rn : rv;
        float mn = INFINITY, mx = -INFINITY;
        for (int n = tid; n < N_; n += 256) { float v = r[n]; mn = fminf(mn, v); mx = fmaxf(mx, v); }
        red[tid] = mn; sbuf[tid] = mx;
        __syncthreads();
        for (int s = 128; s > 0; s >>= 1) {
            if (tid < s) { red[tid] = fminf(red[tid], red[tid + s]); sbuf[tid] = fmaxf(sbuf[tid], sbuf[tid + s]); }
            __syncthreads();
        }
        mn = red[0]; mx = sbuf[0];
        __syncthreads();
        float inv = 1.0f / (mx - mn);
        for (int n = tid; n < N_; n += 256) r[n] = (r[n] - mn) * inv;
        __syncthreads();
        for (int i = tid; i < 2048; i += 256) sbuf[i] = (i < N_) ? r[i] : -INFINITY;
        __syncthreads();
        // ascending bitonic sort of 2048
        for (int k = 2; k <= 2048; k <<= 1) {
            for (int j = k >> 1; j > 0; j >>= 1) {
                for (int i = tid; i < 2048; i += 256) {
                    int ixj = i ^ j;
                    if (ixj > i) {
                        bool up = ((i & k) == 0);
                        float a0 = sbuf[i], b0 = sbuf[ixj];
                        if ((a0 > b0) == up) { sbuf[i] = b0; sbuf[ixj] = a0; }
                    }
                }
                __syncthreads();
            }
        }
        if (tid == 0) thrs[br] = sbuf[2048 - NTOK_];
        __syncthreads();
    }

    float tv = thrs[0], tn = thrs[1];
    for (int n = tid; n < N_; n += 256) {
        float a = rv[n]; a = (a >= tv) ? a : 0.0f;
        float c2 = rn[n]; c2 = (c2 >= tn) ? c2 : 0.0f;
        g_cam[b * N_ + n] = fmaxf(a, c2);
    }
}

// ---------------- kernel 3/5: loss init / finalize ----------------
__global__ void init_kernel() { g_loss = 0.0f; }
__global__ void final_kernel(float* out) { out[0] = g_loss * (1.0f / (float)(B_ * N_)); }

// ---------------- kernel 4: conv-GEMM + ReLU + score + BCE ----------------
// Block tile: M=128 (two t-slices of one b, each padded 49->64), N=512 (4x128), K=2304.
// A = implicit im2col via per-row pointers into the shared x slice (row 98 = zeros).
#define XSTR 264          // xsm row stride (bf16 elems), conflict-free
#define WSTR 72           // wsm row stride (bf16 elems), conflict-free
#define XSM_BYTES (99 * XSTR * 2)           // 52272 -> pad 52288
#define WSM_OFF   52288
#define WSM_BYTES (2 * 128 * WSTR * 2)      // 36864
#define SROW_OFF  (WSM_OFF + WSM_BYTES)     // 89152
#define SWSM_OFF  (SROW_OFF + 512)
#define CBSM_OFF  (SWSM_OFF + 2048)
#define REDB_OFF  (CBSM_OFF + 2048)
#define SMEM_GEMM (REDB_OFF + 64)

__global__ __launch_bounds__(256, 2)
void gemm_kernel(const float* __restrict__ conv_b,
                 const float* __restrict__ score_w,
                 const float* __restrict__ score_b) {
    extern __shared__ char smem[];
    __nv_bfloat16* xsm = (__nv_bfloat16*)smem;
    __nv_bfloat16* wsm = (__nv_bfloat16*)(smem + WSM_OFF);
    float* srow = (float*)(smem + SROW_OFF);
    float* swsm = (float*)(smem + SWSM_OFF);
    float* cbsm = (float*)(smem + CBSM_OFF);
    float* redb = (float*)(smem + REDB_OFF);

    int tid = threadIdx.x;
    int lane = tid & 31, wid = tid >> 5;
    int g = lane >> 2, tg = lane & 3;
    int warp_m = wid & 3, warp_n = wid >> 2;
    int m_base = warp_m * 32;

    int blk = blockIdx.x;
    int b = blk >> 4;
    int t0 = (blk & 15) * 2;

    // ---- fill x slice (rows 0..97 data, row 98 zeros) ----
    for (int i = tid; i < 98 * 32; i += 256) {
        int row = i >> 5, seg = i & 31;
        int slice = (row >= 49) ? 1 : 0;
        int pos = row - slice * 49;
        const __nv_bfloat16* src =
            g_xT + ((size_t)((b * T_ + t0 + slice) * HW_ + pos)) * C_ + seg * 8;
        *(uint4*)(xsm + row * XSTR + seg * 8) = *(const uint4*)src;
    }
    if (tid < 128) ((uint32_t*)(xsm + 98 * XSTR))[tid] = 0u;
    for (int i = tid; i < 512; i += 256) { swsm[i] = score_w[i]; cbsm[i] = conv_b[i]; }
    if (tid < 128) srow[tid] = 0.0f;

    int wrow = tid >> 1, wseg = tid & 1;   // weight-tile loader role: 2 threads/row

    for (int nt = 0; nt < 4; ++nt) {
        int d_tile = nt * 128;
        float acc[2][8][4];
#pragma unroll
        for (int mf = 0; mf < 2; ++mf)
#pragma unroll
            for (int nf = 0; nf < 8; ++nf)
#pragma unroll
                for (int q = 0; q < 4; ++q) acc[mf][nf][q] = 0.0f;

        // prologue: stage 0 weights -> wsm[0]
        {
            const uint4* src = (const uint4*)(g_W + ((size_t)(d_tile + wrow)) * C_ + wseg * 32);
            uint4* dst = (uint4*)(wsm + wrow * WSTR + wseg * 32);
#pragma unroll
            for (int q = 0; q < 4; ++q) dst[q] = src[q];
        }
        __syncthreads();

        int buf = 0;
        for (int s = 0; s < 36; ++s) {
            int tap = s >> 2;
            int c0 = (s & 3) << 6;

            // async prefetch next weight tile into other buffer
            int sn = s + 1;
            if (sn < 36) {
                int tapn = sn >> 2, c0n = (sn & 3) << 6;
                const __nv_bfloat16* src =
                    g_W + ((size_t)(tapn * D_ + d_tile + wrow)) * C_ + c0n + wseg * 32;
                uint32_t dsts = (uint32_t)__cvta_generic_to_shared(
                    wsm + (buf ^ 1) * (128 * WSTR) + wrow * WSTR + wseg * 32);
#pragma unroll
                for (int q = 0; q < 4; ++q) cp_async16(dsts + q * 16, src + q * 8);
                cp_commit();
            }

            // per-tap A row offsets (shifted conv window; OOB/pad -> zero row 98)
            int dh = tap / 3 - 1, dw = tap % 3 - 1;
            int aoff[2][2];
#pragma unroll
            for (int mf = 0; mf < 2; ++mf) {
#pragma unroll
                for (int hh = 0; hh < 2; ++hh) {
                    int r = m_base + mf * 16 + hh * 8 + g;
                    int slice = r >> 6, pos = r & 63;
                    int xr = 98;
                    if (pos < 49) {
                        int h = pos / 7, w = pos % 7;
                        int ph = h + dh, pw = w + dw;
                        if (ph >= 0 && ph < 7 && pw >= 0 && pw < 7)
                            xr = slice * 49 + ph * 7 + pw;
                    }
                    aoff[mf][hh] = xr * XSTR;
                }
            }

            const __nv_bfloat16* wb = wsm + buf * (128 * WSTR);
#pragma unroll
            for (int k16 = 0; k16 < 4; ++k16) {
                int kl = k16 * 16;
                uint32_t a[2][4];
#pragma unroll
                for (int mf = 0; mf < 2; ++mf) {
                    int cA = c0 + kl + tg * 2;
                    a[mf][0] = *(const uint32_t*)(xsm + aoff[mf][0] + cA);
                    a[mf][1] = *(const uint32_t*)(xsm + aoff[mf][1] + cA);
                    a[mf][2] = *(const uint32_t*)(xsm + aoff[mf][0] + cA + 8);
                    a[mf][3] = *(const uint32_t*)(xsm + aoff[mf][1] + cA + 8);
                }
#pragma unroll
                for (int nf = 0; nf < 8; ++nf) {
                    int nrow = warp_n * 64 + nf * 8 + g;
                    uint32_t b0 = *(const uint32_t*)(wb + nrow * WSTR + kl + tg * 2);
                    uint32_t b1 = *(const uint32_t*)(wb + nrow * WSTR + kl + tg * 2 + 8);
                    mma16816(acc[0][nf], a[0], b0, b1);
                    mma16816(acc[1][nf], a[1], b0, b1);
                }
            }

            cp_wait0();
            __syncthreads();
            buf ^= 1;
        }

        // epilogue: fused bias + ReLU + score_w dot, accumulate per-row
#pragma unroll
        for (int mf = 0; mf < 2; ++mf) {
            float p0 = 0.f, p1 = 0.f;
#pragma unroll
            for (int nf = 0; nf < 8; ++nf) {
                int d = d_tile + warp_n * 64 + nf * 8 + tg * 2;
                float cb0 = cbsm[d], cb1 = cbsm[d + 1];
                float sw0 = swsm[d], sw1 = swsm[d + 1];
                p0 += sw0 * fmaxf(acc[mf][nf][0] + cb0, 0.f)
                    + sw1 * fmaxf(acc[mf][nf][1] + cb1, 0.f);
                p1 += sw0 * fmaxf(acc[mf][nf][2] + cb0, 0.f)
                    + sw1 * fmaxf(acc[mf][nf][3] + cb1, 0.f);
            }
            p0 += __shfl_xor_sync(0xffffffff, p0, 1);
            p0 += __shfl_xor_sync(0xffffffff, p0, 2);
            p1 += __shfl_xor_sync(0xffffffff, p1, 1);
            p1 += __shfl_xor_sync(0xffffffff, p1, 2);
            if (tg == 0) {
                atomicAdd(&srow[m_base + mf * 16 + g], p0);
                atomicAdd(&srow[m_base + mf * 16 + 8 + g], p1);
            }
        }
        __syncthreads();
    }

    // ---- BCE over the 98 valid rows, block-reduce, one global atomic ----
    float lsum = 0.0f;
    if (tid < 128) {
        int slice = tid >> 6, pos = tid & 63;
        if (pos < 49) {
            float sl = srow[tid] + score_b[0];
            int t = t0 + slice;
            float y = g_cam[b * N_ + t * HW_ + pos];
            float bce = log1pf(expf(-fabsf(sl)))
                      + ((sl > 0.f) ? (1.f - y) * sl : -sl * y);
            lsum = bce;
        }
    }
#pragma unroll
    for (int o = 16; o > 0; o >>= 1) lsum += __shfl_xor_sync(0xffffffff, lsum, o);
    if (lane == 0) redb[wid] = lsum;
    __syncthreads();
    if (tid == 0) {
        float s2 = 0.f;
#pragma unroll
        for (int i = 0; i < 8; ++i) s2 += redb[i];
        atomicAdd(&g_loss, s2);
    }
}

// ---------------- launcher ----------------
extern "C" void kernel_launch(void* const* d_in, const int* in_sizes, int n_in,
                              void* d_out, int out_size) {
    const float* x        = (const float*)d_in[0];
    const float* lv       = (const float*)d_in[1];
    const float* ln       = (const float*)d_in[2];
    const float* wpv      = (const float*)d_in[3];
    const float* wpn      = (const float*)d_in[4];
    const float* conv_w   = (const float*)d_in[5];
    const float* conv_b   = (const float*)d_in[6];
    const float* score_w  = (const float*)d_in[7];
    const float* score_b  = (const float*)d_in[8];
    float* out = (float*)d_out;

    cudaFuncSetAttribute(gemm_kernel, cudaFuncAttributeMaxDynamicSharedMemorySize, SMEM_GEMM);

    prep_w_kernel<<<(9 * D_ * C_ + 255) / 256, 256>>>(conv_w);
    prep_x_kernel<<<B_ * T_, 256>>>(x);
    cam_kernel<<<B_, 256>>>(x, lv, ln, wpv, wpn);
    init_kernel<<<1, 1>>>();
    gemm_kernel<<<B_ * T_ / 2, 256, SMEM_GEMM>>>(conv_b, score_w, score_b);
    final_kernel<<<1, 1>>>(out);
}